// round 8
// baseline (speedup 1.0000x reference)
#include <cuda_runtime.h>
#include <cuda_fp16.h>
#include <math.h>
#include <stdint.h>

// Problem constants
#define NB     16
#define NPGC   1000
#define NNODE  16000
#define DDIM   512
#define DGOUT  256
#define NHEAD  8
#define NEDGE  256000
#define EPG    16000        // edges per graph (edge list is graph-sorted)
#define EPSBN  1e-5f
#define FROWS  32           // rows per GIN block
#define EROUND 2000         // edges per collection round (worst-case list cap)
#define NROUND (EPG / EROUND)

// NO __device__ global arrays: any module data segment tested (2.5..232 MB)
// forced the driver context heap to grow by a fresh 128 MB chunk inside the
// harness's memory-checkpoint window. All scratch lives inside d_out:
//   fp16 H ping-pong: low half [half idx 0, 8.192M), high half [8.192M, 16.384M)
//   attention scratch: reuses the (dead) high half after layer 3
//   final n_level fp32 produced by an in-place fp16->fp32 expansion
#define HB_HALF  8192000          // half-index of the high half
#define NL_ELEMS (NNODE * DDIM)   // 8,192,000

// ---------------------------------------------------------------------------
// Utility / degree kernels
// ---------------------------------------------------------------------------
__global__ void fillk(float* p, int n, float v) {
    int i = blockIdx.x * blockDim.x + threadIdx.x;
    if (i < n) p[i] = v;
}

__global__ void edge_deg(const int* __restrict__ dst, float* __restrict__ deg) {
    int e = blockIdx.x * blockDim.x + threadIdx.x;
    if (e < NEDGE) atomicAdd(&deg[dst[e]], 1.0f);
}

__global__ void deg_finish(const float* __restrict__ deg, float* __restrict__ dis,
                           float* __restrict__ c) {
    int i = blockIdx.x * blockDim.x + threadIdx.x;
    if (i < NNODE) {
        float d = rsqrtf(deg[i]);
        dis[i] = d;
        c[i]   = d * d;
    }
}

__global__ void edge_cvec(const int* __restrict__ src, const int* __restrict__ dst,
                          const float* __restrict__ dis, float* __restrict__ c) {
    int e = blockIdx.x * blockDim.x + threadIdx.x;
    if (e < NEDGE) atomicAdd(&c[dst[e]], dis[src[e]] * dis[dst[e]]);
}

// ---------------------------------------------------------------------------
// Fused GIN layer: Hout = relu(relu((Hin + scatter(Hin)) @ W1 + b1) @ W2 + b2)
//                  [+ Hin residual]   — Hin != Hout, so all graphs in 1 launch.
// Block = 32 rows of one graph. Agg tile in smem (fp32); weights streamed.
// Dynamic smem: 32*512*4 + 16*512*4 + 2000*8 + 16 = 114,320 B.
// ---------------------------------------------------------------------------
template <typename TIN>
__global__ __launch_bounds__(256) void gin_layer(
    const TIN* __restrict__ Hin, __half* __restrict__ Hout,
    const int* __restrict__ src, const int* __restrict__ dst,
    const float* __restrict__ W1, const float* __restrict__ b1,
    const float* __restrict__ W2, const float* __restrict__ b2, int res)
{
    extern __shared__ float sm[];
    float* Ssm = sm;                             // [32][512] agg, later T
    float* Wsm = sm + FROWS * DDIM;              // [16][512] weight slab
    int2*  ml  = (int2*)(Wsm + 16 * DDIM);       // match list (EROUND)
    int*   cnt = (int*)(ml + EROUND);

    int t = threadIdx.x;
    int g = blockIdx.x >> 5;
    int r0 = (blockIdx.x & 31) * FROWS;
    int gbase = g * NPGC;

    // self rows
    for (int idx = t; idx < FROWS * DDIM; idx += 256) {
        int gr = r0 + (idx >> 9);
        Ssm[idx] = (gr < NPGC) ? (float)Hin[(size_t)(gbase + gr) * DDIM + (idx & 511)] : 0.f;
    }
    __syncthreads();

    // aggregation: scan this graph's edges in rounds, gather matching src rows
    int ebase = g * EPG;
    int wid = t >> 5, lane = t & 31;
    for (int rd = 0; rd < NROUND; rd++) {
        if (t == 0) *cnt = 0;
        __syncthreads();
        int e0 = ebase + rd * EROUND;
        for (int e = e0 + t; e < e0 + EROUND; e += 256) {
            int dl = __ldg(&dst[e]) - gbase - r0;
            if (dl >= 0 && dl < FROWS) {
                int pos = atomicAdd(cnt, 1);
                ml[pos] = make_int2(__ldg(&src[e]), dl);
            }
        }
        __syncthreads();
        int nm = *cnt;
        for (int m = wid; m < nm; m += 8) {
            int2 me = ml[m];
            const TIN* srow = Hin + (size_t)me.x * DDIM;
            float* drow = Ssm + me.y * DDIM;
#pragma unroll
            for (int jj = 0; jj < 16; jj++) {
                int c = lane + jj * 32;
                atomicAdd(&drow[c], (float)srow[c]);
            }
        }
        __syncthreads();
    }

    // MLP: thread handles 8 rows (rg*8+rr) x 8 cols (ct + j*64)
    int rg = t >> 6, ct = t & 63;
    float acc[8][8];

    // Phase 1: T = relu(S @ W1 + b1)
#pragma unroll
    for (int rr = 0; rr < 8; rr++)
#pragma unroll
        for (int j = 0; j < 8; j++) acc[rr][j] = 0.f;
    for (int kt = 0; kt < DDIM; kt += 16) {
        const float4* Wg = (const float4*)(W1 + (size_t)kt * DDIM);
        float4* W4 = (float4*)Wsm;
        for (int i = t; i < 16 * DDIM / 4; i += 256) W4[i] = Wg[i];
        __syncthreads();
#pragma unroll
        for (int kk = 0; kk < 16; kk++) {
            float s[8];
#pragma unroll
            for (int rr = 0; rr < 8; rr++) s[rr] = Ssm[(rg * 8 + rr) * DDIM + kt + kk];
#pragma unroll
            for (int j = 0; j < 8; j++) {
                float w = Wsm[kk * DDIM + ct + j * 64];
#pragma unroll
                for (int rr = 0; rr < 8; rr++) acc[rr][j] += s[rr] * w;
            }
        }
        __syncthreads();
    }
#pragma unroll
    for (int rr = 0; rr < 8; rr++)
#pragma unroll
        for (int j = 0; j < 8; j++) {
            int c = ct + j * 64;
            Ssm[(rg * 8 + rr) * DDIM + c] = fmaxf(acc[rr][j] + b1[c], 0.f);
        }
    __syncthreads();

    // Phase 2: out = relu(T @ W2 + b2) [+ residual]
#pragma unroll
    for (int rr = 0; rr < 8; rr++)
#pragma unroll
        for (int j = 0; j < 8; j++) acc[rr][j] = 0.f;
    for (int kt = 0; kt < DDIM; kt += 16) {
        const float4* Wg = (const float4*)(W2 + (size_t)kt * DDIM);
        float4* W4 = (float4*)Wsm;
        for (int i = t; i < 16 * DDIM / 4; i += 256) W4[i] = Wg[i];
        __syncthreads();
#pragma unroll
        for (int kk = 0; kk < 16; kk++) {
            float s[8];
#pragma unroll
            for (int rr = 0; rr < 8; rr++) s[rr] = Ssm[(rg * 8 + rr) * DDIM + kt + kk];
#pragma unroll
            for (int j = 0; j < 8; j++) {
                float w = Wsm[kk * DDIM + ct + j * 64];
#pragma unroll
                for (int rr = 0; rr < 8; rr++) acc[rr][j] += s[rr] * w;
            }
        }
        __syncthreads();
    }
#pragma unroll
    for (int rr = 0; rr < 8; rr++) {
        int gr = r0 + rg * 8 + rr;
        if (gr < NPGC) {
            size_t base = (size_t)(gbase + gr) * DDIM;
#pragma unroll
            for (int j = 0; j < 8; j++) {
                int c = ct + j * 64;
                float v = fmaxf(acc[rr][j] + b2[c], 0.f);
                if (res) v += (float)Hin[base + c];
                Hout[base + c] = __float2half(v);
            }
        }
    }
}

// ---------------------------------------------------------------------------
// BatchNorm on fp16 H (fp32 accumulation; stats buffer = 2048 floats:
// [0..1024) sums/sumsq, [1024..1536) mean, [1536..2048) rstd)
// ---------------------------------------------------------------------------
__global__ void bn_stats(const __half* __restrict__ X, float* __restrict__ stats) {
    int rows_per = NNODE / gridDim.x;
    int r0 = blockIdx.x * rows_per;
    int c0 = threadIdx.x, c1 = threadIdx.x + 256;
    float s0 = 0.f, q0 = 0.f, s1 = 0.f, q1 = 0.f;
    for (int r = r0; r < r0 + rows_per; r++) {
        float v0 = (float)X[(size_t)r * DDIM + c0];
        float v1 = (float)X[(size_t)r * DDIM + c1];
        s0 += v0; q0 += v0 * v0;
        s1 += v1; q1 += v1 * v1;
    }
    atomicAdd(&stats[c0], s0);
    atomicAdd(&stats[DDIM + c0], q0);
    atomicAdd(&stats[c1], s1);
    atomicAdd(&stats[DDIM + c1], q1);
}

__global__ void bn_finish(float* __restrict__ stats) {
    int c = blockIdx.x * blockDim.x + threadIdx.x;
    if (c >= DDIM) return;
    float m = stats[c] / (float)NNODE;
    float v = stats[DDIM + c] / (float)NNODE - m * m;
    stats[1024 + c] = m;
    stats[1536 + c] = rsqrtf(v + EPSBN);
}

__global__ void bn_apply(__half* __restrict__ X, const float* __restrict__ stats,
                         const float* __restrict__ gma, const float* __restrict__ bta) {
    size_t i = (size_t)blockIdx.x * blockDim.x + threadIdx.x;
    if (i >= (size_t)NNODE * DDIM) return;
    int c = (int)(i & 511);
    float v = ((float)X[i] - stats[1024 + c]) * stats[1536 + c] * gma[c] + bta[c];
    X[i] = __float2half(v);
}

// ---------------------------------------------------------------------------
// vec[1,512] @ W[512,512] (+bias) -> Y[512]
// ---------------------------------------------------------------------------
__global__ void vecmat512(const float* __restrict__ v, const float* __restrict__ W,
                          const float* __restrict__ bias, float* __restrict__ Y) {
    int c = blockIdx.x * blockDim.x + threadIdx.x;
    if (c >= DDIM) return;
    float a = bias ? bias[c] : 0.f;
#pragma unroll 4
    for (int k = 0; k < DDIM; k++) a += v[k] * W[(size_t)k * DDIM + c];
    Y[c] = a;
}

// ---------------------------------------------------------------------------
// Folded GMT attention (pool p=1 only; pool 0 is dead code).
// ---------------------------------------------------------------------------
__global__ void qk_kernel(const float* __restrict__ k_w1, const float* __restrict__ lin1_w,
                          const float* __restrict__ lin1_b, const float* __restrict__ k_b1,
                          const float* __restrict__ Qs, float* __restrict__ QK,
                          float* __restrict__ alpha, float* __restrict__ beta) {
    int h = blockIdx.x, t = threadIdx.x;
    __shared__ float qs[64], ts[DDIM], red[256];
    if (t < 64) qs[t] = Qs[h * 64 + t];
    __syncthreads();
    for (int m = t; m < DDIM; m += 256) {
        float a = 0.f;
#pragma unroll 4
        for (int d = 0; d < 64; d++) a += k_w1[(size_t)m * DDIM + h * 64 + d] * qs[d];
        ts[m] = a;
    }
    __syncthreads();
    for (int j = t; j < DDIM; j += 256) {
        float a = 0.f;
#pragma unroll 4
        for (int m = 0; m < DDIM; m++) a += lin1_w[(size_t)j * DDIM + m] * ts[m];
        QK[h * DDIM + j] = a;
    }
    red[t] = lin1_b[t] * ts[t] + lin1_b[t + 256] * ts[t + 256];
    __syncthreads();
    for (int o = 128; o; o >>= 1) {
        if (t < o) red[t] += red[t + o];
        __syncthreads();
    }
    if (t == 0) alpha[h] = red[0];
    if (t == 1) {
        float bs = 0.f;
        for (int d = 0; d < 64; d++) bs += k_b1[h * 64 + d] * qs[d];
        beta[h] = bs;
    }
}

// z[h][n] = QK_h . H[n], 16 nodes x 8 heads per block (128 threads)
__global__ __launch_bounds__(128) void z_kernel(const __half* __restrict__ X,
                                                const float* __restrict__ QK,
                                                float* __restrict__ zw) {
    __shared__ __half xs[16 * DDIM];
    __shared__ float qs[NHEAD * DDIM];
    int t = threadIdx.x;
    int n0 = blockIdx.x * 16;
    for (int i = t; i < NHEAD * DDIM; i += 128) qs[i] = QK[i];
    const uint32_t* Xg = (const uint32_t*)(X + (size_t)n0 * DDIM);
    uint32_t* xs4 = (uint32_t*)xs;
    for (int i = t; i < 16 * DDIM / 2; i += 128) xs4[i] = Xg[i];
    __syncthreads();
    int nl = t >> 3, h = t & 7;
    const __half* row = xs + nl * DDIM;
    const float* q = qs + h * DDIM;
    float s = 0.f;
#pragma unroll 8
    for (int c = 0; c < DDIM; c++) s += (float)row[c] * q[c];
    zw[h * NNODE + n0 + nl] = s;
}

__global__ void sc_init(const float* __restrict__ zw, const float* __restrict__ dis,
                        const float* __restrict__ c, const float* __restrict__ alpha,
                        const float* __restrict__ beta, float* __restrict__ sc) {
    int i = blockIdx.x * blockDim.x + threadIdx.x;
    if (i >= NNODE) return;
    float d2 = dis[i] * dis[i];
    float ci = c[i];
#pragma unroll
    for (int h = 0; h < NHEAD; h++)
        sc[h * NNODE + i] = d2 * zw[h * NNODE + i] + ci * alpha[h] + beta[h];
}

__global__ void sc_scatter(const int* __restrict__ src, const int* __restrict__ dst,
                           const float* __restrict__ dis, const float* __restrict__ zw,
                           float* __restrict__ sc) {
    int e = blockIdx.x * blockDim.x + threadIdx.x;
    if (e >= NEDGE) return;
    int s = src[e], d = dst[e];
    float co = dis[s] * dis[d];
#pragma unroll
    for (int h = 0; h < NHEAD; h++)
        atomicAdd(&sc[h * NNODE + d], co * zw[h * NNODE + s]);
}

__global__ void softmax_k(float* __restrict__ sc, const float* __restrict__ c,
                          float* __restrict__ gam) {
    int b = blockIdx.x, h = blockIdx.y;
    float* s = sc + h * NNODE + b * NPGC;
    const float* cc = c + b * NPGC;
    __shared__ float red[256];
    int t = threadIdx.x;
    float m = -1e30f;
    for (int k = t; k < NPGC; k += 256) m = fmaxf(m, s[k]);
    red[t] = m;
    __syncthreads();
    for (int o = 128; o; o >>= 1) {
        if (t < o) red[t] = fmaxf(red[t], red[t + o]);
        __syncthreads();
    }
    m = red[0];
    __syncthreads();
    const float scale = 0.044194173824159216f;  // 1/sqrt(512)
    float sum = 0.f;
    for (int k = t; k < NPGC; k += 256) {
        float p = __expf((s[k] - m) * scale);
        s[k] = p;
        sum += p;
    }
    red[t] = sum;
    __syncthreads();
    for (int o = 128; o; o >>= 1) {
        if (t < o) red[t] += red[t + o];
        __syncthreads();
    }
    float inv = 1.f / red[0];
    __syncthreads();
    float g = 0.f;
    for (int k = t; k < NPGC; k += 256) {
        float a = s[k] * inv;
        s[k] = a;
        g += a * cc[k];
    }
    red[t] = g;
    __syncthreads();
    for (int o = 128; o; o >>= 1) {
        if (t < o) red[t] += red[t + o];
        __syncthreads();
    }
    if (t == 0) gam[b * NHEAD + h] = red[0];
}

__global__ void w_init(const float* __restrict__ sc, const float* __restrict__ dis,
                       float* __restrict__ zw) {
    int i = blockIdx.x * blockDim.x + threadIdx.x;
    if (i >= NNODE) return;
    float d2 = dis[i] * dis[i];
#pragma unroll
    for (int h = 0; h < NHEAD; h++)
        zw[h * NNODE + i] = sc[h * NNODE + i] * d2;
}

__global__ void w_scatter(const int* __restrict__ src, const int* __restrict__ dst,
                          const float* __restrict__ dis, const float* __restrict__ sc,
                          float* __restrict__ zw) {
    int e = blockIdx.x * blockDim.x + threadIdx.x;
    if (e >= NEDGE) return;
    int s = src[e], d = dst[e];
    float co = dis[s] * dis[d];
#pragma unroll
    for (int h = 0; h < NHEAD; h++)
        atomicAdd(&zw[h * NNODE + s], co * sc[h * NNODE + d]);
}

__global__ __launch_bounds__(256) void uassemble(
    const __half* __restrict__ X, const float* __restrict__ lin1_w,
    const float* __restrict__ v_w1, const float* __restrict__ v_b1,
    const float* __restrict__ zw, const float* __restrict__ gam,
    const float* __restrict__ Qs, const float* __restrict__ bv0,
    float* __restrict__ att)
{
    int bb = blockIdx.x, h = blockIdx.y;
    __shared__ float ws[NPGC];
    __shared__ float us[DDIM];
    __shared__ float uv[DDIM];
    int t = threadIdx.x;
    for (int j = t; j < NPGC; j += 256) ws[j] = zw[h * NNODE + bb * NPGC + j];
    __syncthreads();
    float a0 = 0.f, a1 = 0.f;
    const __half* xb = X + (size_t)bb * NPGC * DDIM;
    for (int j = 0; j < NPGC; j++) {
        float wj = ws[j];
        a0 += wj * (float)xb[(size_t)j * DDIM + t];
        a1 += wj * (float)xb[(size_t)j * DDIM + t + 256];
    }
    us[t] = a0;
    us[t + 256] = a1;
    __syncthreads();
    float c0 = 0.f, c1 = 0.f;
    for (int j = 0; j < DDIM; j++) {
        float u = us[j];
        c0 += u * lin1_w[(size_t)j * DDIM + t];
        c1 += u * lin1_w[(size_t)j * DDIM + t + 256];
    }
    uv[t] = c0;
    uv[t + 256] = c1;
    __syncthreads();
    if (t < 64) {
        int d = h * 64 + t;
        float o = 0.f;
        for (int m = 0; m < DDIM; m++) o += uv[m] * v_w1[(size_t)m * DDIM + d];
        att[bb * DDIM + d] = Qs[d] + o + gam[bb * NHEAD + h] * bv0[d] + v_b1[d];
    }
}

// ---------------------------------------------------------------------------
// LayerNorm / tail
// ---------------------------------------------------------------------------
__global__ void ln_rows(const float* __restrict__ X, float* __restrict__ Y,
                        const float* __restrict__ g, const float* __restrict__ b) {
    __shared__ float red[256];
    int r = blockIdx.x, t = threadIdx.x;
    float v0 = X[(size_t)r * DDIM + t];
    float v1 = X[(size_t)r * DDIM + t + 256];
    red[t] = v0 + v1;
    __syncthreads();
    for (int s = 128; s > 0; s >>= 1) {
        if (t < s) red[t] += red[t + s];
        __syncthreads();
    }
    float mean = red[0] / (float)DDIM;
    __syncthreads();
    float d0 = v0 - mean, d1 = v1 - mean;
    red[t] = d0 * d0 + d1 * d1;
    __syncthreads();
    for (int s = 128; s > 0; s >>= 1) {
        if (t < s) red[t] += red[t + s];
        __syncthreads();
    }
    float rstd = rsqrtf(red[0] / (float)DDIM + EPSBN);
    Y[(size_t)r * DDIM + t]       = d0 * rstd * g[t] + b[t];
    Y[(size_t)r * DDIM + t + 256] = d1 * rstd * g[t + 256] + b[t + 256];
}

__global__ void rowmat_relu_add(const float* __restrict__ X, const float* __restrict__ W,
                                const float* __restrict__ bias, float* __restrict__ Y) {
    __shared__ float xr[DDIM];
    int r = blockIdx.x, t = threadIdx.x;
    xr[t] = X[(size_t)r * DDIM + t];
    xr[t + 256] = X[(size_t)r * DDIM + t + 256];
    __syncthreads();
    for (int cc = t; cc < DDIM; cc += 256) {
        float a = bias[cc];
#pragma unroll 4
        for (int k = 0; k < DDIM; k++) a += xr[k] * W[(size_t)k * DDIM + cc];
        Y[(size_t)r * DDIM + cc] = X[(size_t)r * DDIM + cc] + fmaxf(a, 0.f);
    }
}

__global__ void lin2_k(const float* __restrict__ X, const float* __restrict__ W,
                       const float* __restrict__ bias, float* __restrict__ Y) {
    __shared__ float xr[DDIM];
    int r = blockIdx.x, t = threadIdx.x;
    xr[t] = X[(size_t)r * DDIM + t];
    xr[t + 256] = X[(size_t)r * DDIM + t + 256];
    __syncthreads();
    float a = bias[t];
#pragma unroll 4
    for (int k = 0; k < DDIM; k++) a += xr[k] * W[(size_t)k * DGOUT + t];
    Y[(size_t)r * DGOUT + t] = a;
}

// ---------------------------------------------------------------------------
// In-place fp16 (low half) -> fp32 expansion. Chunk [lo,hi): writes bytes
// [4lo,4hi) never touch remaining reads [0,2lo) since 4lo >= 2lo; in-chunk
// disjoint since 2hi <= 4lo when lo = ceil(hi/2). Launch order = descending.
// ---------------------------------------------------------------------------
__global__ void expand_chunk(float* __restrict__ f, int lo, int hi) {
    int i = lo + blockIdx.x * blockDim.x + threadIdx.x;
    if (i < hi) {
        const __half* h = (const __half*)f;
        f[i] = (float)h[i];
    }
}

__global__ void expand_small(float* __restrict__ f, int n) {
    const __half* h = (const __half*)f;
    int t = threadIdx.x;
    float v = 0.f;
    if (t < n) v = (float)h[t];
    __syncthreads();
    if (t < n) f[t] = v;
}

// ---------------------------------------------------------------------------
// Host launch
// ---------------------------------------------------------------------------
extern "C" void kernel_launch(void* const* d_in, const int* in_sizes, int n_in,
                              void* d_out, int out_size) {
    const float* x       = (const float*)d_in[0];
    const int*   ei      = (const int*)d_in[1];
    const float* gin_w1  = (const float*)d_in[3];
    const float* gin_b1  = (const float*)d_in[4];
    const float* gin_w2  = (const float*)d_in[5];
    const float* gin_b2  = (const float*)d_in[6];
    const float* bn_g    = (const float*)d_in[7];
    const float* bn_b    = (const float*)d_in[8];
    const float* lin1_w  = (const float*)d_in[9];
    const float* lin1_b  = (const float*)d_in[10];
    const float* lin2_w  = (const float*)d_in[11];
    const float* lin2_b  = (const float*)d_in[12];
    const float* S2      = (const float*)d_in[14];
    const float* q_w     = (const float*)d_in[15];
    const float* q_b     = (const float*)d_in[16];
    const float* k_w     = (const float*)d_in[17];
    const float* k_b     = (const float*)d_in[18];
    const float* v_w     = (const float*)d_in[19];
    const float* v_b     = (const float*)d_in[20];
    const float* o_w     = (const float*)d_in[21];
    const float* o_b     = (const float*)d_in[22];
    const float* ln0_g   = (const float*)d_in[23];
    const float* ln0_b   = (const float*)d_in[24];
    const float* ln1_g   = (const float*)d_in[25];
    const float* ln1_b   = (const float*)d_in[26];

    const int* src = ei;
    const int* dst = ei + NEDGE;
    float* out_f = (float*)d_out;
    float* g_level = out_f + NL_ELEMS;            // [16, 256] at the tail

    __half* Hlo = (__half*)d_out;                 // low half  (halves [0, 8.192M))
    __half* Hhi = (__half*)d_out + HB_HALF;       // high half (halves [8.192M, 16.384M))
    float*  SB  = out_f + NL_ELEMS / 2;           // fp32 view of the high half

    // Attention scratch layout inside SB (floats)
    float* s_dis  = SB + 0;        // 16000
    float* s_c    = SB + 16000;    // 16000
    float* s_deg  = SB + 32000;    // 16000
    float* s_sc   = SB + 48000;    // 8*16000
    float* s_zw   = SB + 176000;   // 8*16000
    float* s_QK   = SB + 304000;   // 4096
    float* s_Qs   = SB + 308096;   // 512
    float* s_bv0  = SB + 308608;   // 512
    float* s_alp  = SB + 309120;   // 8
    float* s_bet  = SB + 309128;   // 8
    float* s_gam  = SB + 309136;   // 128
    float* s_att  = SB + 309264;   // 8192
    float* s_t16  = SB + 317456;   // 8192
    float* s_bx   = SB + 325648;   // 8192

    const int T = 256;
    const size_t DD = (size_t)DDIM * DDIM;
    const int edge_grid = (NEDGE + T - 1) / T;
    const int node_grid = (NNODE + T - 1) / T;
    const int gin_smem = (FROWS * DDIM + 16 * DDIM) * (int)sizeof(float)
                       + EROUND * (int)sizeof(int2) + 16;

    cudaFuncSetAttribute(gin_layer<float>, cudaFuncAttributeMaxDynamicSharedMemorySize, gin_smem);
    cudaFuncSetAttribute(gin_layer<__half>, cudaFuncAttributeMaxDynamicSharedMemorySize, gin_smem);

    // ---- 3 GIN layers (fp16 ping-pong: x->lo, lo->hi, hi->lo) ----
    // BN stats buffer lives in whichever half is currently dead.
    for (int i = 0; i < 3; i++) {
        __half* Hout;
        float* stats;
        if (i == 0) {
            Hout = Hlo; stats = SB;                      // high half untouched yet
            gin_layer<float><<<NB * 32, T, gin_smem>>>(
                x, Hout, src, dst,
                gin_w1 + (size_t)i * DD, gin_b1 + i * DDIM,
                gin_w2 + (size_t)i * DD, gin_b2 + i * DDIM, 0);
        } else if (i == 1) {
            Hout = Hhi; stats = out_f;                   // low half dead after this layer
            gin_layer<__half><<<NB * 32, T, gin_smem>>>(
                Hlo, Hout, src, dst,
                gin_w1 + (size_t)i * DD, gin_b1 + i * DDIM,
                gin_w2 + (size_t)i * DD, gin_b2 + i * DDIM, 1);
        } else {
            Hout = Hlo; stats = SB;                      // high half dead after this layer
            gin_layer<__half><<<NB * 32, T, gin_smem>>>(
                Hhi, Hout, src, dst,
                gin_w1 + (size_t)i * DD, gin_b1 + i * DDIM,
                gin_w2 + (size_t)i * DD, gin_b2 + i * DDIM, 1);
        }
        fillk<<<(2 * DDIM + T - 1) / T, T>>>(stats, 2 * DDIM, 0.0f);
        bn_stats<<<128, T>>>(Hout, stats);
        bn_finish<<<(DDIM + T - 1) / T, T>>>(stats);
        bn_apply<<<(int)(((size_t)NNODE * DDIM + T - 1) / T), T>>>(
            Hout, stats, bn_g + i * DDIM, bn_b + i * DDIM);
    }
    // Final fp16 H in low half; high half free for attention scratch.

    // ---- degree / normalization coefficients ----
    fillk<<<node_grid, T>>>(s_deg, NNODE, 1.0f);
    edge_deg<<<edge_grid, T>>>(dst, s_deg);
    deg_finish<<<node_grid, T>>>(s_deg, s_dis, s_c);
    edge_cvec<<<edge_grid, T>>>(src, dst, s_dis, s_c);

    // ---- folded GMT attention (single seed; pool 0 dead) ----
    const float* k_w1 = k_w + DD;
    const float* v_w1 = v_w + DD;
    vecmat512<<<2, T>>>(S2, q_w + DD, q_b + DDIM, s_Qs);
    vecmat512<<<2, T>>>(lin1_b, v_w1, nullptr, s_bv0);
    qk_kernel<<<NHEAD, T>>>(k_w1, lin1_w, lin1_b, k_b + DDIM, s_Qs, s_QK, s_alp, s_bet);
    z_kernel<<<NNODE / 16, 128>>>(Hlo, s_QK, s_zw);
    sc_init<<<node_grid, T>>>(s_zw, s_dis, s_c, s_alp, s_bet, s_sc);
    sc_scatter<<<edge_grid, T>>>(src, dst, s_dis, s_zw, s_sc);
    {
        dim3 sg(NB, NHEAD);
        softmax_k<<<sg, T>>>(s_sc, s_c, s_gam);
    }
    w_init<<<node_grid, T>>>(s_sc, s_dis, s_zw);
    w_scatter<<<edge_grid, T>>>(src, dst, s_dis, s_sc, s_zw);
    {
        dim3 ug(NB, NHEAD);
        uassemble<<<ug, T>>>(Hlo, lin1_w, v_w1, v_b + DDIM, s_zw, s_gam, s_Qs, s_bv0, s_att);
    }

    // ---- tail: LN -> residual MLP -> LN -> final linear (writes g_level) ----
    ln_rows<<<NB, T>>>(s_att, s_t16, ln0_g + DDIM, ln0_b + DDIM);
    rowmat_relu_add<<<NB, T>>>(s_t16, o_w + DD, o_b + DDIM, s_att);
    ln_rows<<<NB, T>>>(s_att, s_bx, ln1_g + DDIM, ln1_b + DDIM);
    lin2_k<<<NB, T>>>(s_bx, lin2_w, lin2_b, g_level);

    // ---- expand fp16 low-half H into fp32 n_level (in place, descending) ----
    int hi = NL_ELEMS;
    while (hi > 256) {
        int lo = (hi + 1) / 2;
        int cnt = hi - lo;
        expand_chunk<<<(cnt + T - 1) / T, T>>>(out_f, lo, hi);
        hi = lo;
    }
    expand_small<<<1, 256>>>(out_f, hi);

    (void)in_sizes; (void)n_in; (void)out_size;
}

// round 10
// speedup vs baseline: 1.8830x; 1.8830x over previous
#include <cuda_runtime.h>
#include <cuda_fp16.h>
#include <math.h>
#include <stdint.h>

// Problem constants
#define NB     16
#define NPGC   1000
#define NNODE  16000
#define DDIM   512
#define DGOUT  256
#define NHEAD  8
#define NEDGE  256000
#define EPG    16000        // edges per graph (edge list is graph-sorted)
#define EPSBN  1e-5f
#define FROWS  32           // rows per GIN block
#define EROUND 2000         // edges per collection round (worst-case list cap)
#define NROUND (EPG / EROUND)

#define SPITCH 516          // S tile pitch (floats): banks (4*row + k) all distinct
#define WPITCH 520          // W tile pitch (floats): banks (8*k + n) all distinct
#define KC     16           // K-chunk for weight streaming

// NO __device__ global arrays: any module data segment (2.5..232 MB tested)
// forces the driver context heap to grow by a 128 MB chunk inside the
// harness's memory-checkpoint window. All scratch lives inside d_out.
#define HB_HALF  8192000          // half-index of the high half
#define NL_ELEMS (NNODE * DDIM)   // 8,192,000

// ---------------------------------------------------------------------------
// tf32 helpers
// ---------------------------------------------------------------------------
__device__ __forceinline__ uint32_t f2tf32(float f) {
    uint32_t r;
    asm("cvt.rna.tf32.f32 %0, %1;" : "=r"(r) : "f"(f));
    return r;
}

__device__ __forceinline__ void mma_tf32(float* c, uint32_t a0, uint32_t a1,
                                         uint32_t a2, uint32_t a3,
                                         uint32_t b0, uint32_t b1) {
    asm volatile(
        "mma.sync.aligned.m16n8k8.row.col.f32.tf32.tf32.f32 "
        "{%0,%1,%2,%3}, {%4,%5,%6,%7}, {%8,%9}, {%0,%1,%2,%3};"
        : "+f"(c[0]), "+f"(c[1]), "+f"(c[2]), "+f"(c[3])
        : "r"(a0), "r"(a1), "r"(a2), "r"(a3), "r"(b0), "r"(b1));
}

// ---------------------------------------------------------------------------
// Utility / degree kernels
// ---------------------------------------------------------------------------
__global__ void fillk(float* p, int n, float v) {
    int i = blockIdx.x * blockDim.x + threadIdx.x;
    if (i < n) p[i] = v;
}

__global__ void edge_deg(const int* __restrict__ dst, float* __restrict__ deg) {
    int e = blockIdx.x * blockDim.x + threadIdx.x;
    if (e < NEDGE) atomicAdd(&deg[dst[e]], 1.0f);
}

__global__ void deg_finish(const float* __restrict__ deg, float* __restrict__ dis,
                           float* __restrict__ c) {
    int i = blockIdx.x * blockDim.x + threadIdx.x;
    if (i < NNODE) {
        float d = rsqrtf(deg[i]);
        dis[i] = d;
        c[i]   = d * d;
    }
}

__global__ void edge_cvec(const int* __restrict__ src, const int* __restrict__ dst,
                          const float* __restrict__ dis, float* __restrict__ c) {
    int e = blockIdx.x * blockDim.x + threadIdx.x;
    if (e < NEDGE) atomicAdd(&c[dst[e]], dis[src[e]] * dis[dst[e]]);
}

// ---------------------------------------------------------------------------
// Fused GIN layer (tf32 tensor-core MLP + atomic-free aggregation):
//   Hout = relu(relu((Hin + scatter(Hin)) @ W1 + b1) @ W2 + b2) [+ Hin]
// Block = 32 rows of one graph; Hin != Hout so all graphs in one launch.
// smem: S[32][SPITCH] f32 + W[KC][WPITCH] f32 (tf32-rounded) + match list.
// ---------------------------------------------------------------------------
template <typename TIN>
__global__ __launch_bounds__(256) void gin_layer(
    const TIN* __restrict__ Hin, __half* __restrict__ Hout,
    const int* __restrict__ src, const int* __restrict__ dst,
    const float* __restrict__ W1, const float* __restrict__ b1,
    const float* __restrict__ W2, const float* __restrict__ b2, int res)
{
    extern __shared__ float sm[];
    float* Ssm = sm;                             // [32][SPITCH] agg, later T
    float* Wsm = sm + FROWS * SPITCH;            // [KC][WPITCH] tf32-rounded weights
    int2*  ml  = (int2*)(Wsm + KC * WPITCH);     // match list (EROUND)
    int*   cnt = (int*)(ml + EROUND);

    int t = threadIdx.x;
    int gph = blockIdx.x >> 5;
    int r0 = (blockIdx.x & 31) * FROWS;
    int gbase = gph * NPGC;
    int w = t >> 5, lane = t & 31;

    // self rows (zero the padding rows)
    for (int idx = t; idx < FROWS * DDIM; idx += 256) {
        int rr = idx >> 9, c = idx & 511;
        int gr = r0 + rr;
        Ssm[rr * SPITCH + c] =
            (gr < NPGC) ? (float)Hin[(size_t)(gbase + gr) * DDIM + c] : 0.f;
    }
    __syncthreads();

    // aggregation, atomic-free: warp w exclusively owns dl in [4w, 4w+4)
    int ebase = gph * EPG;
    for (int rd = 0; rd < NROUND; rd++) {
        if (t == 0) *cnt = 0;
        __syncthreads();
        int e0 = ebase + rd * EROUND;
        for (int e = e0 + t; e < e0 + EROUND; e += 256) {
            int dl = __ldg(&dst[e]) - gbase - r0;
            if (dl >= 0 && dl < FROWS) {
                int pos = atomicAdd(cnt, 1);
                ml[pos] = make_int2(__ldg(&src[e]), dl);
            }
        }
        __syncthreads();
        int nm = *cnt;
        for (int m = 0; m < nm; m++) {
            int2 me = ml[m];
            if ((me.y >> 2) == w) {
                const TIN* srow = Hin + (size_t)me.x * DDIM;
                float* drow = Ssm + me.y * SPITCH;
#pragma unroll
                for (int jj = 0; jj < 16; jj++) {
                    int c = lane + jj * 32;
                    drow[c] += (float)srow[c];
                }
            }
        }
        __syncthreads();
    }

    // mma tiling: warp -> rows rb..rb+15, cols cb..cb+127 (16 n8 frags)
    int g8 = lane >> 2, tg = lane & 3;
    int rb = (w >> 2) * 16;
    int cb = (w & 3) * 128;
    float acc[16][4];

    // ---- Phase 1: T = relu(S @ W1 + b1) ----
#pragma unroll
    for (int f = 0; f < 16; f++)
#pragma unroll
        for (int j = 0; j < 4; j++) acc[f][j] = 0.f;

    for (int kt = 0; kt < DDIM; kt += KC) {
        for (int i = t; i < KC * 128; i += 256) {
            int kr = i >> 7, c4 = (i & 127) << 2;
            float4 v = *(const float4*)(W1 + (size_t)(kt + kr) * DDIM + c4);
            float* wr = Wsm + kr * WPITCH + c4;
            wr[0] = __uint_as_float(f2tf32(v.x));
            wr[1] = __uint_as_float(f2tf32(v.y));
            wr[2] = __uint_as_float(f2tf32(v.z));
            wr[3] = __uint_as_float(f2tf32(v.w));
        }
        __syncthreads();
#pragma unroll
        for (int ks = 0; ks < KC; ks += 8) {
            uint32_t a0 = f2tf32(Ssm[(rb + g8) * SPITCH + kt + ks + tg]);
            uint32_t a1 = f2tf32(Ssm[(rb + g8 + 8) * SPITCH + kt + ks + tg]);
            uint32_t a2 = f2tf32(Ssm[(rb + g8) * SPITCH + kt + ks + tg + 4]);
            uint32_t a3 = f2tf32(Ssm[(rb + g8 + 8) * SPITCH + kt + ks + tg + 4]);
#pragma unroll
            for (int f = 0; f < 16; f++) {
                int col = cb + f * 8 + g8;
                uint32_t b0 = __float_as_uint(Wsm[(ks + tg) * WPITCH + col]);
                uint32_t b1r = __float_as_uint(Wsm[(ks + tg + 4) * WPITCH + col]);
                mma_tf32(acc[f], a0, a1, a2, a3, b0, b1r);
            }
        }
        __syncthreads();
    }
    // write T into Ssm
#pragma unroll
    for (int f = 0; f < 16; f++) {
        int c0 = cb + f * 8 + tg * 2;
        Ssm[(rb + g8) * SPITCH + c0]         = fmaxf(acc[f][0] + b1[c0], 0.f);
        Ssm[(rb + g8) * SPITCH + c0 + 1]     = fmaxf(acc[f][1] + b1[c0 + 1], 0.f);
        Ssm[(rb + g8 + 8) * SPITCH + c0]     = fmaxf(acc[f][2] + b1[c0], 0.f);
        Ssm[(rb + g8 + 8) * SPITCH + c0 + 1] = fmaxf(acc[f][3] + b1[c0 + 1], 0.f);
    }
    __syncthreads();

    // ---- Phase 2: out = relu(T @ W2 + b2) [+ residual] ----
#pragma unroll
    for (int f = 0; f < 16; f++)
#pragma unroll
        for (int j = 0; j < 4; j++) acc[f][j] = 0.f;

    for (int kt = 0; kt < DDIM; kt += KC) {
        for (int i = t; i < KC * 128; i += 256) {
            int kr = i >> 7, c4 = (i & 127) << 2;
            float4 v = *(const float4*)(W2 + (size_t)(kt + kr) * DDIM + c4);
            float* wr = Wsm + kr * WPITCH + c4;
            wr[0] = __uint_as_float(f2tf32(v.x));
            wr[1] = __uint_as_float(f2tf32(v.y));
            wr[2] = __uint_as_float(f2tf32(v.z));
            wr[3] = __uint_as_float(f2tf32(v.w));
        }
        __syncthreads();
#pragma unroll
        for (int ks = 0; ks < KC; ks += 8) {
            uint32_t a0 = f2tf32(Ssm[(rb + g8) * SPITCH + kt + ks + tg]);
            uint32_t a1 = f2tf32(Ssm[(rb + g8 + 8) * SPITCH + kt + ks + tg]);
            uint32_t a2 = f2tf32(Ssm[(rb + g8) * SPITCH + kt + ks + tg + 4]);
            uint32_t a3 = f2tf32(Ssm[(rb + g8 + 8) * SPITCH + kt + ks + tg + 4]);
#pragma unroll
            for (int f = 0; f < 16; f++) {
                int col = cb + f * 8 + g8;
                uint32_t b0 = __float_as_uint(Wsm[(ks + tg) * WPITCH + col]);
                uint32_t b1r = __float_as_uint(Wsm[(ks + tg + 4) * WPITCH + col]);
                mma_tf32(acc[f], a0, a1, a2, a3, b0, b1r);
            }
        }
        __syncthreads();
    }

    // epilogue -> global fp16
    int gr0 = r0 + rb + g8;       // rows gr0, gr0+8
#pragma unroll
    for (int f = 0; f < 16; f++) {
        int c0 = cb + f * 8 + tg * 2;
        if (gr0 < NPGC) {
            size_t base = (size_t)(gbase + gr0) * DDIM;
            float v0 = fmaxf(acc[f][0] + b2[c0], 0.f);
            float v1 = fmaxf(acc[f][1] + b2[c0 + 1], 0.f);
            if (res) { v0 += (float)Hin[base + c0]; v1 += (float)Hin[base + c0 + 1]; }
            Hout[base + c0]     = __float2half(v0);
            Hout[base + c0 + 1] = __float2half(v1);
        }
        if (gr0 + 8 < NPGC) {
            size_t base = (size_t)(gbase + gr0 + 8) * DDIM;
            float v0 = fmaxf(acc[f][2] + b2[c0], 0.f);
            float v1 = fmaxf(acc[f][3] + b2[c0 + 1], 0.f);
            if (res) { v0 += (float)Hin[base + c0]; v1 += (float)Hin[base + c0 + 1]; }
            Hout[base + c0]     = __float2half(v0);
            Hout[base + c0 + 1] = __float2half(v1);
        }
    }
}

// ---------------------------------------------------------------------------
// BatchNorm on fp16 H (fp32 accumulation; stats: [0,1024) sums/sq, mean@1024,
// rstd@1536)
// ---------------------------------------------------------------------------
__global__ void bn_stats(const __half* __restrict__ X, float* __restrict__ stats) {
    int rows_per = NNODE / gridDim.x;
    int r0 = blockIdx.x * rows_per;
    int c0 = threadIdx.x, c1 = threadIdx.x + 256;
    float s0 = 0.f, q0 = 0.f, s1 = 0.f, q1 = 0.f;
    for (int r = r0; r < r0 + rows_per; r++) {
        float v0 = (float)X[(size_t)r * DDIM + c0];
        float v1 = (float)X[(size_t)r * DDIM + c1];
        s0 += v0; q0 += v0 * v0;
        s1 += v1; q1 += v1 * v1;
    }
    atomicAdd(&stats[c0], s0);
    atomicAdd(&stats[DDIM + c0], q0);
    atomicAdd(&stats[c1], s1);
    atomicAdd(&stats[DDIM + c1], q1);
}

__global__ void bn_finish(float* __restrict__ stats) {
    int c = blockIdx.x * blockDim.x + threadIdx.x;
    if (c >= DDIM) return;
    float m = stats[c] / (float)NNODE;
    float v = stats[DDIM + c] / (float)NNODE - m * m;
    stats[1024 + c] = m;
    stats[1536 + c] = rsqrtf(v + EPSBN);
}

__global__ void bn_apply(__half* __restrict__ X, const float* __restrict__ stats,
                         const float* __restrict__ gma, const float* __restrict__ bta) {
    size_t i = (size_t)blockIdx.x * blockDim.x + threadIdx.x;
    if (i >= (size_t)NNODE * DDIM) return;
    int c = (int)(i & 511);
    float v = ((float)X[i] - stats[1024 + c]) * stats[1536 + c] * gma[c] + bta[c];
    X[i] = __float2half(v);
}

// ---------------------------------------------------------------------------
// vec[1,512] @ W[512,512] (+bias) -> Y[512]
// ---------------------------------------------------------------------------
__global__ void vecmat512(const float* __restrict__ v, const float* __restrict__ W,
                          const float* __restrict__ bias, float* __restrict__ Y) {
    int c = blockIdx.x * blockDim.x + threadIdx.x;
    if (c >= DDIM) return;
    float a = bias ? bias[c] : 0.f;
#pragma unroll 4
    for (int k = 0; k < DDIM; k++) a += v[k] * W[(size_t)k * DDIM + c];
    Y[c] = a;
}

// ---------------------------------------------------------------------------
// Folded GMT attention (pool p=1 only; pool 0 is dead code).
// ---------------------------------------------------------------------------
__global__ void qk_kernel(const float* __restrict__ k_w1, const float* __restrict__ lin1_w,
                          const float* __restrict__ lin1_b, const float* __restrict__ k_b1,
                          const float* __restrict__ Qs, float* __restrict__ QK,
                          float* __restrict__ alpha, float* __restrict__ beta) {
    int h = blockIdx.x, t = threadIdx.x;
    __shared__ float qs[64], ts[DDIM], red[256];
    if (t < 64) qs[t] = Qs[h * 64 + t];
    __syncthreads();
    for (int m = t; m < DDIM; m += 256) {
        float a = 0.f;
#pragma unroll 4
        for (int d = 0; d < 64; d++) a += k_w1[(size_t)m * DDIM + h * 64 + d] * qs[d];
        ts[m] = a;
    }
    __syncthreads();
    for (int j = t; j < DDIM; j += 256) {
        float a = 0.f;
#pragma unroll 4
        for (int m = 0; m < DDIM; m++) a += lin1_w[(size_t)j * DDIM + m] * ts[m];
        QK[h * DDIM + j] = a;
    }
    red[t] = lin1_b[t] * ts[t] + lin1_b[t + 256] * ts[t + 256];
    __syncthreads();
    for (int o = 128; o; o >>= 1) {
        if (t < o) red[t] += red[t + o];
        __syncthreads();
    }
    if (t == 0) alpha[h] = red[0];
    if (t == 1) {
        float bs = 0.f;
        for (int d = 0; d < 64; d++) bs += k_b1[h * 64 + d] * qs[d];
        beta[h] = bs;
    }
}

__global__ __launch_bounds__(128) void z_kernel(const __half* __restrict__ X,
                                                const float* __restrict__ QK,
                                                float* __restrict__ zw) {
    __shared__ __half xs[16 * DDIM];
    __shared__ float qs[NHEAD * DDIM];
    int t = threadIdx.x;
    int n0 = blockIdx.x * 16;
    for (int i = t; i < NHEAD * DDIM; i += 128) qs[i] = QK[i];
    const uint32_t* Xg = (const uint32_t*)(X + (size_t)n0 * DDIM);
    uint32_t* xs4 = (uint32_t*)xs;
    for (int i = t; i < 16 * DDIM / 2; i += 128) xs4[i] = Xg[i];
    __syncthreads();
    int nl = t >> 3, h = t & 7;
    const __half* row = xs + nl * DDIM;
    const float* q = qs + h * DDIM;
    float s = 0.f;
#pragma unroll 8
    for (int c = 0; c < DDIM; c++) s += (float)row[c] * q[c];
    zw[h * NNODE + n0 + nl] = s;
}

__global__ void sc_init(const float* __restrict__ zw, const float* __restrict__ dis,
                        const float* __restrict__ c, const float* __restrict__ alpha,
                        const float* __restrict__ beta, float* __restrict__ sc) {
    int i = blockIdx.x * blockDim.x + threadIdx.x;
    if (i >= NNODE) return;
    float d2 = dis[i] * dis[i];
    float ci = c[i];
#pragma unroll
    for (int h = 0; h < NHEAD; h++)
        sc[h * NNODE + i] = d2 * zw[h * NNODE + i] + ci * alpha[h] + beta[h];
}

__global__ void sc_scatter(const int* __restrict__ src, const int* __restrict__ dst,
                           const float* __restrict__ dis, const float* __restrict__ zw,
                           float* __restrict__ sc) {
    int e = blockIdx.x * blockDim.x + threadIdx.x;
    if (e >= NEDGE) return;
    int s = src[e], d = dst[e];
    float co = dis[s] * dis[d];
#pragma unroll
    for (int h = 0; h < NHEAD; h++)
        atomicAdd(&sc[h * NNODE + d], co * zw[h * NNODE + s]);
}

__global__ void softmax_k(float* __restrict__ sc, const float* __restrict__ c,
                          float* __restrict__ gam) {
    int b = blockIdx.x, h = blockIdx.y;
    float* s = sc + h * NNODE + b * NPGC;
    const float* cc = c + b * NPGC;
    __shared__ float red[256];
    int t = threadIdx.x;
    float m = -1e30f;
    for (int k = t; k < NPGC; k += 256) m = fmaxf(m, s[k]);
    red[t] = m;
    __syncthreads();
    for (int o = 128; o; o >>= 1) {
        if (t < o) red[t] = fmaxf(red[t], red[t + o]);
        __syncthreads();
    }
    m = red[0];
    __syncthreads();
    const float scale = 0.044194173824159216f;  // 1/sqrt(512)
    float sum = 0.f;
    for (int k = t; k < NPGC; k += 256) {
        float p = __expf((s[k] - m) * scale);
        s[k] = p;
        sum += p;
    }
    red[t] = sum;
    __syncthreads();
    for (int o = 128; o; o >>= 1) {
        if (t < o) red[t] += red[t + o];
        __syncthreads();
    }
    float inv = 1.f / red[0];
    __syncthreads();
    float g = 0.f;
    for (int k = t; k < NPGC; k += 256) {
        float a = s[k] * inv;
        s[k] = a;
        g += a * cc[k];
    }
    red[t] = g;
    __syncthreads();
    for (int o = 128; o; o >>= 1) {
        if (t < o) red[t] += red[t + o];
        __syncthreads();
    }
    if (t == 0) gam[b * NHEAD + h] = red[0];
}

__global__ void w_init(const float* __restrict__ sc, const float* __restrict__ dis,
                       float* __restrict__ zw) {
    int i = blockIdx.x * blockDim.x + threadIdx.x;
    if (i >= NNODE) return;
    float d2 = dis[i] * dis[i];
#pragma unroll
    for (int h = 0; h < NHEAD; h++)
        zw[h * NNODE + i] = sc[h * NNODE + i] * d2;
}

__global__ void w_scatter(const int* __restrict__ src, const int* __restrict__ dst,
                          const float* __restrict__ dis, const float* __restrict__ sc,
                          float* __restrict__ zw) {
    int e = blockIdx.x * blockDim.x + threadIdx.x;
    if (e >= NEDGE) return;
    int s = src[e], d = dst[e];
    float co = dis[s] * dis[d];
#pragma unroll
    for (int h = 0; h < NHEAD; h++)
        atomicAdd(&zw[h * NNODE + s], co * sc[h * NNODE + d]);
}

__global__ __launch_bounds__(256) void uassemble(
    const __half* __restrict__ X, const float* __restrict__ lin1_w,
    const float* __restrict__ v_w1, const float* __restrict__ v_b1,
    const float* __restrict__ zw, const float* __restrict__ gam,
    const float* __restrict__ Qs, const float* __restrict__ bv0,
    float* __restrict__ att)
{
    int bb = blockIdx.x, h = blockIdx.y;
    __shared__ float ws[NPGC];
    __shared__ float us[DDIM];
    __shared__ float uv[DDIM];
    int t = threadIdx.x;
    for (int j = t; j < NPGC; j += 256) ws[j] = zw[h * NNODE + bb * NPGC + j];
    __syncthreads();
    float a0 = 0.f, a1 = 0.f;
    const __half* xb = X + (size_t)bb * NPGC * DDIM;
    for (int j = 0; j < NPGC; j++) {
        float wj = ws[j];
        a0 += wj * (float)xb[(size_t)j * DDIM + t];
        a1 += wj * (float)xb[(size_t)j * DDIM + t + 256];
    }
    us[t] = a0;
    us[t + 256] = a1;
    __syncthreads();
    float c0 = 0.f, c1 = 0.f;
    for (int j = 0; j < DDIM; j++) {
        float u = us[j];
        c0 += u * lin1_w[(size_t)j * DDIM + t];
        c1 += u * lin1_w[(size_t)j * DDIM + t + 256];
    }
    uv[t] = c0;
    uv[t + 256] = c1;
    __syncthreads();
    if (t < 64) {
        int d = h * 64 + t;
        float o = 0.f;
        for (int m = 0; m < DDIM; m++) o += uv[m] * v_w1[(size_t)m * DDIM + d];
        att[bb * DDIM + d] = Qs[d] + o + gam[bb * NHEAD + h] * bv0[d] + v_b1[d];
    }
}

// ---------------------------------------------------------------------------
// LayerNorm / tail
// ---------------------------------------------------------------------------
__global__ void ln_rows(const float* __restrict__ X, float* __restrict__ Y,
                        const float* __restrict__ g, const float* __restrict__ b) {
    __shared__ float red[256];
    int r = blockIdx.x, t = threadIdx.x;
    float v0 = X[(size_t)r * DDIM + t];
    float v1 = X[(size_t)r * DDIM + t + 256];
    red[t] = v0 + v1;
    __syncthreads();
    for (int s = 128; s > 0; s >>= 1) {
        if (t < s) red[t] += red[t + s];
        __syncthreads();
    }
    float mean = red[0] / (float)DDIM;
    __syncthreads();
    float d0 = v0 - mean, d1 = v1 - mean;
    red[t] = d0 * d0 + d1 * d1;
    __syncthreads();
    for (int s = 128; s > 0; s >>= 1) {
        if (t < s) red[t] += red[t + s];
        __syncthreads();
    }
    float rstd = rsqrtf(red[0] / (float)DDIM + EPSBN);
    Y[(size_t)r * DDIM + t]       = d0 * rstd * g[t] + b[t];
    Y[(size_t)r * DDIM + t + 256] = d1 * rstd * g[t + 256] + b[t + 256];
}

__global__ void rowmat_relu_add(const float* __restrict__ X, const float* __restrict__ W,
                                const float* __restrict__ bias, float* __restrict__ Y) {
    __shared__ float xr[DDIM];
    int r = blockIdx.x, t = threadIdx.x;
    xr[t] = X[(size_t)r * DDIM + t];
    xr[t + 256] = X[(size_t)r * DDIM + t + 256];
    __syncthreads();
    for (int cc = t; cc < DDIM; cc += 256) {
        float a = bias[cc];
#pragma unroll 4
        for (int k = 0; k < DDIM; k++) a += xr[k] * W[(size_t)k * DDIM + cc];
        Y[(size_t)r * DDIM + cc] = X[(size_t)r * DDIM + cc] + fmaxf(a, 0.f);
    }
}

__global__ void lin2_k(const float* __restrict__ X, const float* __restrict__ W,
                       const float* __restrict__ bias, float* __restrict__ Y) {
    __shared__ float xr[DDIM];
    int r = blockIdx.x, t = threadIdx.x;
    xr[t] = X[(size_t)r * DDIM + t];
    xr[t + 256] = X[(size_t)r * DDIM + t + 256];
    __syncthreads();
    float a = bias[t];
#pragma unroll 4
    for (int k = 0; k < DDIM; k++) a += xr[k] * W[(size_t)k * DGOUT + t];
    Y[(size_t)r * DGOUT + t] = a;
}

// ---------------------------------------------------------------------------
// In-place fp16 (low half) -> fp32 expansion (descending chunks, race-free)
// ---------------------------------------------------------------------------
__global__ void expand_chunk(float* __restrict__ f, int lo, int hi) {
    int i = lo + blockIdx.x * blockDim.x + threadIdx.x;
    if (i < hi) {
        const __half* h = (const __half*)f;
        f[i] = (float)h[i];
    }
}

__global__ void expand_small(float* __restrict__ f, int n) {
    const __half* h = (const __half*)f;
    int t = threadIdx.x;
    float v = 0.f;
    if (t < n) v = (float)h[t];
    __syncthreads();
    if (t < n) f[t] = v;
}

// ---------------------------------------------------------------------------
// Host launch
// ---------------------------------------------------------------------------
extern "C" void kernel_launch(void* const* d_in, const int* in_sizes, int n_in,
                              void* d_out, int out_size) {
    const float* x       = (const float*)d_in[0];
    const int*   ei      = (const int*)d_in[1];
    const float* gin_w1  = (const float*)d_in[3];
    const float* gin_b1  = (const float*)d_in[4];
    const float* gin_w2  = (const float*)d_in[5];
    const float* gin_b2  = (const float*)d_in[6];
    const float* bn_g    = (const float*)d_in[7];
    const float* bn_b    = (const float*)d_in[8];
    const float* lin1_w  = (const float*)d_in[9];
    const float* lin1_b  = (const float*)d_in[10];
    const float* lin2_w  = (const float*)d_in[11];
    const float* lin2_b  = (const float*)d_in[12];
    const float* S2      = (const float*)d_in[14];
    const float* q_w     = (const float*)d_in[15];
    const float* q_b     = (const float*)d_in[16];
    const float* k_w     = (const float*)d_in[17];
    const float* k_b     = (const float*)d_in[18];
    const float* v_w     = (const float*)d_in[19];
    const float* v_b     = (const float*)d_in[20];
    const float* o_w     = (const float*)d_in[21];
    const float* o_b     = (const float*)d_in[22];
    const float* ln0_g   = (const float*)d_in[23];
    const float* ln0_b   = (const float*)d_in[24];
    const float* ln1_g   = (const float*)d_in[25];
    const float* ln1_b   = (const float*)d_in[26];

    const int* src = ei;
    const int* dst = ei + NEDGE;
    float* out_f = (float*)d_out;
    float* g_level = out_f + NL_ELEMS;

    __half* Hlo = (__half*)d_out;
    __half* Hhi = (__half*)d_out + HB_HALF;
    float*  SB  = out_f + NL_ELEMS / 2;           // fp32 view of the high half

    // Attention scratch inside SB (floats)
    float* s_dis  = SB + 0;
    float* s_c    = SB + 16000;
    float* s_deg  = SB + 32000;
    float* s_sc   = SB + 48000;
    float* s_zw   = SB + 176000;
    float* s_QK   = SB + 304000;
    float* s_Qs   = SB + 308096;
    float* s_bv0  = SB + 308608;
    float* s_alp  = SB + 309120;
    float* s_bet  = SB + 309128;
    float* s_gam  = SB + 309136;
    float* s_att  = SB + 309264;
    float* s_t16  = SB + 317456;
    float* s_bx   = SB + 325648;

    const int T = 256;
    const size_t DD = (size_t)DDIM * DDIM;
    const int edge_grid = (NEDGE + T - 1) / T;
    const int node_grid = (NNODE + T - 1) / T;
    const int gin_smem = (FROWS * SPITCH + KC * WPITCH) * (int)sizeof(float)
                       + EROUND * (int)sizeof(int2) + 16;

    cudaFuncSetAttribute(gin_layer<float>, cudaFuncAttributeMaxDynamicSharedMemorySize, gin_smem);
    cudaFuncSetAttribute(gin_layer<__half>, cudaFuncAttributeMaxDynamicSharedMemorySize, gin_smem);

    // ---- 3 GIN layers (fp16 ping-pong: x->lo, lo->hi, hi->lo) ----
    for (int i = 0; i < 3; i++) {
        __half* Hout;
        float* stats;
        if (i == 0) {
            Hout = Hlo; stats = SB;
            gin_layer<float><<<NB * 32, T, gin_smem>>>(
                x, Hout, src, dst,
                gin_w1 + (size_t)i * DD, gin_b1 + i * DDIM,
                gin_w2 + (size_t)i * DD, gin_b2 + i * DDIM, 0);
        } else if (i == 1) {
            Hout = Hhi; stats = out_f;
            gin_layer<__half><<<NB * 32, T, gin_smem>>>(
                Hlo, Hout, src, dst,
                gin_w1 + (size_t)i * DD, gin_b1 + i * DDIM,
                gin_w2 + (size_t)i * DD, gin_b2 + i * DDIM, 1);
        } else {
            Hout = Hlo; stats = SB;
            gin_layer<__half><<<NB * 32, T, gin_smem>>>(
                Hhi, Hout, src, dst,
                gin_w1 + (size_t)i * DD, gin_b1 + i * DDIM,
                gin_w2 + (size_t)i * DD, gin_b2 + i * DDIM, 1);
        }
        fillk<<<(2 * DDIM + T - 1) / T, T>>>(stats, 2 * DDIM, 0.0f);
        bn_stats<<<128, T>>>(Hout, stats);
        bn_finish<<<(DDIM + T - 1) / T, T>>>(stats);
        bn_apply<<<(int)(((size_t)NNODE * DDIM + T - 1) / T), T>>>(
            Hout, stats, bn_g + i * DDIM, bn_b + i * DDIM);
    }

    // ---- degree / normalization coefficients ----
    fillk<<<node_grid, T>>>(s_deg, NNODE, 1.0f);
    edge_deg<<<edge_grid, T>>>(dst, s_deg);
    deg_finish<<<node_grid, T>>>(s_deg, s_dis, s_c);
    edge_cvec<<<edge_grid, T>>>(src, dst, s_dis, s_c);

    // ---- folded GMT attention (single seed; pool 0 dead) ----
    const float* k_w1 = k_w + DD;
    const float* v_w1 = v_w + DD;
    vecmat512<<<2, T>>>(S2, q_w + DD, q_b + DDIM, s_Qs);
    vecmat512<<<2, T>>>(lin1_b, v_w1, nullptr, s_bv0);
    qk_kernel<<<NHEAD, T>>>(k_w1, lin1_w, lin1_b, k_b + DDIM, s_Qs, s_QK, s_alp, s_bet);
    z_kernel<<<NNODE / 16, 128>>>(Hlo, s_QK, s_zw);
    sc_init<<<node_grid, T>>>(s_zw, s_dis, s_c, s_alp, s_bet, s_sc);
    sc_scatter<<<edge_grid, T>>>(src, dst, s_dis, s_zw, s_sc);
    {
        dim3 sg(NB, NHEAD);
        softmax_k<<<sg, T>>>(s_sc, s_c, s_gam);
    }
    w_init<<<node_grid, T>>>(s_sc, s_dis, s_zw);
    w_scatter<<<edge_grid, T>>>(src, dst, s_dis, s_sc, s_zw);
    {
        dim3 ug(NB, NHEAD);
        uassemble<<<ug, T>>>(Hlo, lin1_w, v_w1, v_b + DDIM, s_zw, s_gam, s_Qs, s_bv0, s_att);
    }

    // ---- tail: LN -> residual MLP -> LN -> final linear ----
    ln_rows<<<NB, T>>>(s_att, s_t16, ln0_g + DDIM, ln0_b + DDIM);
    rowmat_relu_add<<<NB, T>>>(s_t16, o_w + DD, o_b + DDIM, s_att);
    ln_rows<<<NB, T>>>(s_att, s_bx, ln1_g + DDIM, ln1_b + DDIM);
    lin2_k<<<NB, T>>>(s_bx, lin2_w, lin2_b, g_level);

    // ---- expand fp16 low-half H into fp32 n_level (in place, descending) ----
    int hi = NL_ELEMS;
    while (hi > 256) {
        int lo = (hi + 1) / 2;
        int cnt = hi - lo;
        expand_chunk<<<(cnt + T - 1) / T, T>>>(out_f, lo, hi);
        hi = lo;
    }
    expand_small<<<1, 256>>>(out_f, hi);

    (void)in_sizes; (void)n_in; (void)out_size;
}